// round 15
// baseline (speedup 1.0000x reference)
#include <cuda_runtime.h>
#include <cuda_bf16.h>
#include <cstdint>

#define N_NODES  50000
#define N_EDGES  800000
#define CH       128
#define N_GRAPHS 512
#define OUT_CH   8
#define NSCAN_BLK 196                     // ceil(50000/256)

// ============================ scratch ==============================================
__device__ __align__(16) float g_h[N_NODES * CH];
__device__ __align__(16) float g_yrel[N_NODES * CH];
__device__ __align__(16) float g_yroot[N_NODES * CH];
__device__ __align__(16) float g_pooled[N_GRAPHS * CH];
__device__ __align__(16) float g_cnt[N_GRAPHS];
__device__ int g_degi[N_NODES];
__device__ int g_rowptr[N_NODES + 1];
__device__ int g_cursor[N_NODES];
__device__ int g_csr[N_EDGES];
__device__ int g_blksum[NSCAN_BLK];
__device__ int g_blkoff[NSCAN_BLK];
// W images: [6 mats][hi|mid][128n][128k] bf16, transposed (n-major) for ldmatrix B frags
__device__ __align__(16) __nv_bfloat16 g_wimg[6 * 2 * CH * CH];

__device__ __forceinline__ uint32_t smem_u32(const void* p) {
    uint32_t a;
    asm("{ .reg .u64 t; cvta.to.shared.u64 t, %1; cvt.u32.u64 %0, t; }" : "=r"(a) : "l"(p));
    return a;
}

// ============================ zero init ============================================
__global__ void zero_kernel() {
    int idx = blockIdx.x * blockDim.x + threadIdx.x;
    if (idx < N_NODES) g_degi[idx] = 0;
    if (idx < N_GRAPHS * CH) g_pooled[idx] = 0.f;
    if (idx < N_GRAPHS) g_cnt[idx] = 0.f;
}

// ============================ degree ===============================================
__global__ void deg_kernel(const int* __restrict__ ei) {
    int e = blockIdx.x * blockDim.x + threadIdx.x;
    if (e < N_EDGES) atomicAdd(&g_degi[ei[N_EDGES + e]], 1);
}

// ============================ CSR build: 3-kernel scan + fill ======================
__global__ void scan1_kernel() {
    __shared__ int s[256];
    int idx = blockIdx.x * 256 + threadIdx.x;
    int v = (idx < N_NODES) ? g_degi[idx] : 0;
    s[threadIdx.x] = v;
    __syncthreads();
    for (int o = 128; o > 0; o >>= 1) {
        if (threadIdx.x < o) s[threadIdx.x] += s[threadIdx.x + o];
        __syncthreads();
    }
    if (threadIdx.x == 0) g_blksum[blockIdx.x] = s[0];
}
__global__ void scan2_kernel() {
    __shared__ int s[256];
    int t = threadIdx.x;
    int v = (t < NSCAN_BLK) ? g_blksum[t] : 0;
    s[t] = v;
    __syncthreads();
    for (int o = 1; o < 256; o <<= 1) {
        int add = (t >= o) ? s[t - o] : 0;
        __syncthreads();
        s[t] += add;
        __syncthreads();
    }
    if (t < NSCAN_BLK) g_blkoff[t] = s[t] - v;
    if (t == 0) g_rowptr[N_NODES] = N_EDGES;
}
__global__ void scan3_kernel() {
    __shared__ int s[256];
    int idx = blockIdx.x * 256 + threadIdx.x;
    int t = threadIdx.x;
    int v = (idx < N_NODES) ? g_degi[idx] : 0;
    s[t] = v;
    __syncthreads();
    for (int o = 1; o < 256; o <<= 1) {
        int add = (t >= o) ? s[t - o] : 0;
        __syncthreads();
        s[t] += add;
        __syncthreads();
    }
    if (idx < N_NODES) {
        int excl = g_blkoff[blockIdx.x] + s[t] - v;
        g_rowptr[idx] = excl;
        g_cursor[idx] = excl;
    }
}
__global__ void fill_kernel(const int* __restrict__ ei) {
    int e = blockIdx.x * blockDim.x + threadIdx.x;
    if (e >= N_EDGES) return;
    int d = ei[N_EDGES + e];
    int pos = atomicAdd(&g_cursor[d], 1);
    g_csr[pos] = ei[e];
}

// ============================ W -> bf16x2 transposed images ========================
__global__ void prep_w(const float* __restrict__ W0, const float* __restrict__ W1,
                       const float* __restrict__ W2, const float* __restrict__ W3,
                       const float* __restrict__ W4, const float* __restrict__ W5) {
    const float* Ws[6] = {W0, W1, W2, W3, W4, W5};
    const float* W = Ws[blockIdx.x];
    __nv_bfloat16* hi = g_wimg + (size_t)blockIdx.x * (2 * CH * CH);
    __nv_bfloat16* md = hi + CH * CH;
    for (int i = threadIdx.x; i < CH * CH; i += blockDim.x) {
        int k = i >> 7, n = i & 127;          // W[k][n]
        float f = W[i];
        __nv_bfloat16 h = __float2bfloat16(f);
        __nv_bfloat16 m = __float2bfloat16(f - __bfloat162float(h));
        hi[n * CH + k] = h;                   // transposed: [n][k]
        md[n * CH + k] = m;
    }
}

// ============================ HMMA dual GEMM (N-split, 3 CTA/SM) ===================
// grid (391, 4): y = side*2 + nhalf. CTA tile 128(M) x 64(N), K=128.
// bf16x2 split (hh + hm + mh). W hi/mid (64 rows) in smem; A staged per-ks through
// smem as pre-split bf16 hi/mid (128x16, 32B rows, double-buffered), via ldmatrix.
#define WTILE_B   17408                        // 64 * 272
#define A_STAGE_B 4096                         // 128 rows * 32 B
#define A_BUF_B   (2 * A_STAGE_B)              // hi + mid
#define GEMM_SMEM (2 * WTILE_B + 2 * A_BUF_B)  // 34K + 16K = 50K

__device__ __forceinline__ float4 ldA(const float* A, int mbase, int row, int ks,
                                      int c4, bool tail) {
    int m = mbase + row;
    if (tail && m >= N_NODES) return make_float4(0.f, 0.f, 0.f, 0.f);
    return *(const float4*)(A + (size_t)m * CH + ks * 16 + c4 * 4);
}
__device__ __forceinline__ void stA(char* hi, char* mid, int row, int c4, float4 f) {
    __nv_bfloat162 h01 = __float22bfloat162_rn(make_float2(f.x, f.y));
    __nv_bfloat162 h23 = __float22bfloat162_rn(make_float2(f.z, f.w));
    float2 r01 = make_float2(f.x - __bfloat162float(h01.x), f.y - __bfloat162float(h01.y));
    float2 r23 = make_float2(f.z - __bfloat162float(h23.x), f.w - __bfloat162float(h23.y));
    __nv_bfloat162 m01 = __float22bfloat162_rn(r01);
    __nv_bfloat162 m23 = __float22bfloat162_rn(r23);
    uint2 hv, mv;
    hv.x = *(uint32_t*)&h01; hv.y = *(uint32_t*)&h23;
    mv.x = *(uint32_t*)&m01; mv.y = *(uint32_t*)&m23;
    *(uint2*)(hi  + row * 32 + c4 * 8) = hv;
    *(uint2*)(mid + row * 32 + c4 * 8) = mv;
}

__global__ __launch_bounds__(256, 3)
void gemm_tc(const float* __restrict__ X, int use_x, int layer) {
    extern __shared__ char sm[];
    int tid = threadIdx.x, lane = tid & 31, wid = tid >> 5;
    int mbase = blockIdx.x * 128;
    int side  = blockIdx.y >> 1;
    int nhalf = blockIdx.y & 1;
    const float* A = use_x ? X : g_h;
    bool tail = (mbase + 128 > N_NODES);

    char* abuf[2][2] = {
        { sm + 2 * WTILE_B,             sm + 2 * WTILE_B + A_STAGE_B },
        { sm + 2 * WTILE_B + A_BUF_B,   sm + 2 * WTILE_B + A_BUF_B + A_STAGE_B } };

    // ---- copy this CTA's 64-row halves of W hi/mid into padded smem ---------------
    {
        const uint4* wh = (const uint4*)(g_wimg + (size_t)(layer * 2 + side) * (2 * CH * CH));
        const uint4* wm = wh + 2048;           // CH*CH bf16 = 2048 uint4
        int rbase = nhalf * 64;
        for (int i = tid; i < 1024; i += 256) {
            int r = i >> 4, c = i & 15;
            *(uint4*)(sm + r * 272 + c * 16)           = wh[(rbase + r) * 16 + c];
            *(uint4*)(sm + WTILE_B + r * 272 + c * 16) = wm[(rbase + r) * 16 + c];
        }
    }

    // ---- A stage 0: load, split, store -------------------------------------------
    int prow = tid >> 1;
    int pc0  = (tid & 1) * 2, pc1 = pc0 + 1;
    {
        float4 p0 = ldA(A, mbase, prow, 0, pc0, tail);
        float4 p1 = ldA(A, mbase, prow, 0, pc1, tail);
        stA(abuf[0][0], abuf[0][1], prow, pc0, p0);
        stA(abuf[0][0], abuf[0][1], prow, pc1, p1);
    }
    __syncthreads();

    int mrow = (wid & 3) * 32;                 // 4 warps in M
    int ncol = (wid >> 2) * 32;                // 2 warps in N (local 0/32)
    uint32_t sb    = smem_u32(sm);
    uint32_t b_off = (uint32_t)(ncol + (lane & 7)) * 272u + (uint32_t)((lane >> 3) & 1) * 16u;
    uint32_t a_lane = (uint32_t)(lane & 15) * 32u + (uint32_t)(lane >> 4) * 16u;
    uint32_t a_base0 = sb + 2u * WTILE_B + (uint32_t)mrow * 32u + a_lane;

    float acc[2][4][4];
    #pragma unroll
    for (int mt = 0; mt < 2; mt++)
        #pragma unroll
        for (int nt = 0; nt < 4; nt++)
            #pragma unroll
            for (int q = 0; q < 4; q++) acc[mt][nt][q] = 0.f;

    #pragma unroll
    for (int ks = 0; ks < 8; ks++) {
        float4 p0, p1;
        if (ks < 7) {
            p0 = ldA(A, mbase, prow, ks + 1, pc0, tail);
            p1 = ldA(A, mbase, prow, ks + 1, pc1, tail);
        }
        uint32_t ahi[2][4], amid[2][4];
        uint32_t ab = a_base0 + (uint32_t)(ks & 1) * A_BUF_B;
        #pragma unroll
        for (int mt = 0; mt < 2; mt++) {
            uint32_t ad = ab + (uint32_t)mt * (16u * 32u);
            asm volatile("ldmatrix.sync.aligned.m8n8.x4.shared.b16 {%0,%1,%2,%3}, [%4];"
                : "=r"(ahi[mt][0]), "=r"(ahi[mt][1]), "=r"(ahi[mt][2]), "=r"(ahi[mt][3])
                : "r"(ad));
            asm volatile("ldmatrix.sync.aligned.m8n8.x4.shared.b16 {%0,%1,%2,%3}, [%4];"
                : "=r"(amid[mt][0]), "=r"(amid[mt][1]), "=r"(amid[mt][2]), "=r"(amid[mt][3])
                : "r"(ad + A_STAGE_B));
        }
        #pragma unroll
        for (int nt = 0; nt < 4; nt++) {
            uint32_t bd = sb + b_off + (uint32_t)nt * (8u * 272u) + (uint32_t)ks * 32u;
            uint32_t bh0, bh1, bm0, bm1;
            asm volatile("ldmatrix.sync.aligned.m8n8.x2.shared.b16 {%0,%1}, [%2];"
                : "=r"(bh0), "=r"(bh1) : "r"(bd));
            asm volatile("ldmatrix.sync.aligned.m8n8.x2.shared.b16 {%0,%1}, [%2];"
                : "=r"(bm0), "=r"(bm1) : "r"(bd + WTILE_B));
            #pragma unroll
            for (int mt = 0; mt < 2; mt++) {
                asm volatile(
                    "mma.sync.aligned.m16n8k16.row.col.f32.bf16.bf16.f32 "
                    "{%0,%1,%2,%3}, {%4,%5,%6,%7}, {%8,%9}, {%0,%1,%2,%3};"
                    : "+f"(acc[mt][nt][0]), "+f"(acc[mt][nt][1]),
                      "+f"(acc[mt][nt][2]), "+f"(acc[mt][nt][3])
                    : "r"(ahi[mt][0]), "r"(ahi[mt][1]), "r"(ahi[mt][2]), "r"(ahi[mt][3]),
                      "r"(bh0), "r"(bh1));
                asm volatile(
                    "mma.sync.aligned.m16n8k16.row.col.f32.bf16.bf16.f32 "
                    "{%0,%1,%2,%3}, {%4,%5,%6,%7}, {%8,%9}, {%0,%1,%2,%3};"
                    : "+f"(acc[mt][nt][0]), "+f"(acc[mt][nt][1]),
                      "+f"(acc[mt][nt][2]), "+f"(acc[mt][nt][3])
                    : "r"(ahi[mt][0]), "r"(ahi[mt][1]), "r"(ahi[mt][2]), "r"(ahi[mt][3]),
                      "r"(bm0), "r"(bm1));
                asm volatile(
                    "mma.sync.aligned.m16n8k16.row.col.f32.bf16.bf16.f32 "
                    "{%0,%1,%2,%3}, {%4,%5,%6,%7}, {%8,%9}, {%0,%1,%2,%3};"
                    : "+f"(acc[mt][nt][0]), "+f"(acc[mt][nt][1]),
                      "+f"(acc[mt][nt][2]), "+f"(acc[mt][nt][3])
                    : "r"(amid[mt][0]), "r"(amid[mt][1]), "r"(amid[mt][2]), "r"(amid[mt][3]),
                      "r"(bh0), "r"(bh1));
            }
        }
        if (ks < 7) {
            char* hb = abuf[(ks + 1) & 1][0];
            char* mb = abuf[(ks + 1) & 1][1];
            stA(hb, mb, prow, pc0, p0);
            stA(hb, mb, prow, pc1, p1);
        }
        __syncthreads();
    }

    // ---- epilogue: fp32 stores ---------------------------------------------------
    float* C = side ? g_yroot : g_yrel;
    int gi = lane >> 2, t4 = lane & 3;
    int cbase = nhalf * 64 + ncol;
    #pragma unroll
    for (int mt = 0; mt < 2; mt++) {
        int r0 = mbase + mrow + mt * 16 + gi;
        #pragma unroll
        for (int nt = 0; nt < 4; nt++) {
            int col = cbase + nt * 8 + t4 * 2;
            if (r0 < N_NODES)
                *(float2*)(C + (size_t)r0 * CH + col) =
                    make_float2(acc[mt][nt][0], acc[mt][nt][1]);
            if (r0 + 8 < N_NODES)
                *(float2*)(C + (size_t)(r0 + 8) * CH + col) =
                    make_float2(acc[mt][nt][2], acc[mt][nt][3]);
        }
    }
}

// ============================ fused gather + combine (layers 1-2) ==================
__global__ __launch_bounds__(256)
void gather_combine(const float* __restrict__ brel, int do_relu) {
    int gid = blockIdx.x * blockDim.x + threadIdx.x;
    int i   = gid >> 5;
    if (i >= N_NODES) return;
    int lane = gid & 31;
    int beg = g_rowptr[i], end = g_rowptr[i + 1];

    float4 a0 = make_float4(0.f, 0.f, 0.f, 0.f);
    float4 a1 = make_float4(0.f, 0.f, 0.f, 0.f);
    float4 a2 = make_float4(0.f, 0.f, 0.f, 0.f);
    float4 a3 = make_float4(0.f, 0.f, 0.f, 0.f);
    int e = beg;
    for (; e + 3 < end; e += 4) {
        int s0 = g_csr[e], s1 = g_csr[e + 1], s2 = g_csr[e + 2], s3 = g_csr[e + 3];
        float4 v0 = ((const float4*)(g_yrel + (size_t)s0 * CH))[lane];
        float4 v1 = ((const float4*)(g_yrel + (size_t)s1 * CH))[lane];
        float4 v2 = ((const float4*)(g_yrel + (size_t)s2 * CH))[lane];
        float4 v3 = ((const float4*)(g_yrel + (size_t)s3 * CH))[lane];
        a0.x += v0.x; a0.y += v0.y; a0.z += v0.z; a0.w += v0.w;
        a1.x += v1.x; a1.y += v1.y; a1.z += v1.z; a1.w += v1.w;
        a2.x += v2.x; a2.y += v2.y; a2.z += v2.z; a2.w += v2.w;
        a3.x += v3.x; a3.y += v3.y; a3.z += v3.z; a3.w += v3.w;
    }
    for (; e < end; e++) {
        int s0 = g_csr[e];
        float4 v0 = ((const float4*)(g_yrel + (size_t)s0 * CH))[lane];
        a0.x += v0.x; a0.y += v0.y; a0.z += v0.z; a0.w += v0.w;
    }
    float inv = 1.0f / (float)max(end - beg, 1);
    float4 r = ((const float4*)(g_yroot + (size_t)i * CH))[lane];
    float4 b = ((const float4*)brel)[lane];
    float4 o;
    o.x = (a0.x + a1.x + a2.x + a3.x) * inv + r.x + b.x;
    o.y = (a0.y + a1.y + a2.y + a3.y) * inv + r.y + b.y;
    o.z = (a0.z + a1.z + a2.z + a3.z) * inv + r.z + b.z;
    o.w = (a0.w + a1.w + a2.w + a3.w) * inv + r.w + b.w;
    if (do_relu) {
        o.x = fmaxf(o.x, 0.f); o.y = fmaxf(o.y, 0.f);
        o.z = fmaxf(o.z, 0.f); o.w = fmaxf(o.w, 0.f);
    }
    ((float4*)(g_h + (size_t)i * CH))[lane] = o;
}

// ============================ layer 3: gather + combine + pool =====================
__global__ __launch_bounds__(256)
void gather_combine_pool(const float* __restrict__ brel, const int* __restrict__ batch) {
    int gid = blockIdx.x * blockDim.x + threadIdx.x;
    int i   = gid >> 5;
    if (i >= N_NODES) return;
    int lane = gid & 31;
    int beg = g_rowptr[i], end = g_rowptr[i + 1];

    float4 a0 = make_float4(0.f, 0.f, 0.f, 0.f);
    float4 a1 = make_float4(0.f, 0.f, 0.f, 0.f);
    float4 a2 = make_float4(0.f, 0.f, 0.f, 0.f);
    float4 a3 = make_float4(0.f, 0.f, 0.f, 0.f);
    int e = beg;
    for (; e + 3 < end; e += 4) {
        int s0 = g_csr[e], s1 = g_csr[e + 1], s2 = g_csr[e + 2], s3 = g_csr[e + 3];
        float4 v0 = ((const float4*)(g_yrel + (size_t)s0 * CH))[lane];
        float4 v1 = ((const float4*)(g_yrel + (size_t)s1 * CH))[lane];
        float4 v2 = ((const float4*)(g_yrel + (size_t)s2 * CH))[lane];
        float4 v3 = ((const float4*)(g_yrel + (size_t)s3 * CH))[lane];
        a0.x += v0.x; a0.y += v0.y; a0.z += v0.z; a0.w += v0.w;
        a1.x += v1.x; a1.y += v1.y; a1.z += v1.z; a1.w += v1.w;
        a2.x += v2.x; a2.y += v2.y; a2.z += v2.z; a2.w += v2.w;
        a3.x += v3.x; a3.y += v3.y; a3.z += v3.z; a3.w += v3.w;
    }
    for (; e < end; e++) {
        int s0 = g_csr[e];
        float4 v0 = ((const float4*)(g_yrel + (size_t)s0 * CH))[lane];
        a0.x += v0.x; a0.y += v0.y; a0.z += v0.z; a0.w += v0.w;
    }
    float inv = 1.0f / (float)max(end - beg, 1);
    float4 r = ((const float4*)(g_yroot + (size_t)i * CH))[lane];
    float4 b = ((const float4*)brel)[lane];
    float4 o;
    o.x = (a0.x + a1.x + a2.x + a3.x) * inv + r.x + b.x;
    o.y = (a0.y + a1.y + a2.y + a3.y) * inv + r.y + b.y;
    o.z = (a0.z + a1.z + a2.z + a3.z) * inv + r.z + b.z;
    o.w = (a0.w + a1.w + a2.w + a3.w) * inv + r.w + b.w;
    int bg = batch[i];
    float* p = g_pooled + (size_t)bg * CH + lane * 4;
    asm volatile("red.global.add.v4.f32 [%0], {%1, %2, %3, %4};"
                 :: "l"(p), "f"(o.x), "f"(o.y), "f"(o.z), "f"(o.w) : "memory");
    if (lane == 0) atomicAdd(&g_cnt[bg], 1.0f);
}

// ============================ MLP head =============================================
__global__ void mlp_kernel(const float* __restrict__ W1, const float* __restrict__ b1,
                           const float* __restrict__ W2, const float* __restrict__ b2,
                           const float* __restrict__ Wo, const float* __restrict__ bo,
                           float* __restrict__ out) {
    __shared__ float s0[CH], s1[CH];
    int b = blockIdx.x, t = threadIdx.x;
    float c = fmaxf(g_cnt[b], 1.0f);
    s0[t] = g_pooled[b * CH + t] / c;
    __syncthreads();
    float acc = b1[t];
    #pragma unroll 8
    for (int k = 0; k < CH; k++) acc += s0[k] * W1[k * CH + t];
    s1[t] = fmaxf(acc, 0.f);
    __syncthreads();
    acc = b2[t];
    #pragma unroll 8
    for (int k = 0; k < CH; k++) acc += s1[k] * W2[k * CH + t];
    __syncthreads();
    s0[t] = fmaxf(acc, 0.f);
    __syncthreads();
    if (t < OUT_CH) {
        float a = bo[t];
        #pragma unroll 8
        for (int k = 0; k < CH; k++) a += s0[k] * Wo[k * OUT_CH + t];
        out[b * OUT_CH + t] = a;
    }
}

// ============================ launch ===============================================
extern "C" void kernel_launch(void* const* d_in, const int* in_sizes, int n_in,
                              void* d_out, int out_size) {
    const float* x     = (const float*)d_in[0];
    const int*   ei    = (const int*)d_in[1];
    const int*   batch = (const int*)d_in[2];
    const float* Wrel1 = (const float*)d_in[3];
    const float* brel1 = (const float*)d_in[4];
    const float* Wroot1= (const float*)d_in[5];
    const float* Wrel2 = (const float*)d_in[6];
    const float* brel2 = (const float*)d_in[7];
    const float* Wroot2= (const float*)d_in[8];
    const float* Wrel3 = (const float*)d_in[9];
    const float* brel3 = (const float*)d_in[10];
    const float* Wroot3= (const float*)d_in[11];
    const float* W1 = (const float*)d_in[12];
    const float* b1 = (const float*)d_in[13];
    const float* W2 = (const float*)d_in[14];
    const float* b2 = (const float*)d_in[15];
    const float* Wo = (const float*)d_in[16];
    const float* bo = (const float*)d_in[17];
    float* out = (float*)d_out;

    static int inited = 0;
    static cudaStream_t s1;
    static cudaEvent_t evFork, evJoin;
    if (!inited) {
        cudaFuncSetAttribute(gemm_tc, cudaFuncAttributeMaxDynamicSharedMemorySize, GEMM_SMEM);
        cudaStreamCreateWithFlags(&s1, cudaStreamNonBlocking);
        cudaEventCreateWithFlags(&evFork, cudaEventDisableTiming);
        cudaEventCreateWithFlags(&evJoin, cudaEventDisableTiming);
        inited = 1;
    }

    dim3 ggrid((N_NODES + 127) / 128, 4);                       // 391 x 4
    const int nodew_blocks = (N_NODES * 32 + 255) / 256;        // 6250

    // ---- fork: side stream runs prep_w + gemm layer 1 (needs only x, W) ----------
    cudaEventRecord(evFork, 0);
    cudaStreamWaitEvent(s1, evFork, 0);
    prep_w<<<6, 256, 0, s1>>>(Wrel1, Wroot1, Wrel2, Wroot2, Wrel3, Wroot3);
    gemm_tc<<<ggrid, 256, GEMM_SMEM, s1>>>(x, 1, 0);

    // ---- null stream: CSR build (independent of gemm1) ----------------------------
    zero_kernel<<<(N_GRAPHS * CH + 255) / 256, 256>>>();
    deg_kernel<<<(N_EDGES + 255) / 256, 256>>>(ei);
    scan1_kernel<<<NSCAN_BLK, 256>>>();
    scan2_kernel<<<1, 256>>>();
    scan3_kernel<<<NSCAN_BLK, 256>>>();
    fill_kernel<<<(N_EDGES + 255) / 256, 256>>>(ei);

    // ---- join ---------------------------------------------------------------------
    cudaEventRecord(evJoin, s1);
    cudaStreamWaitEvent(0, evJoin, 0);

    // layer 1 combine
    gather_combine<<<nodew_blocks, 256>>>(brel1, 1);
    // layer 2
    gemm_tc<<<ggrid, 256, GEMM_SMEM>>>(x, 0, 1);
    gather_combine<<<nodew_blocks, 256>>>(brel2, 1);
    // layer 3: gather + combine + pool fused
    gemm_tc<<<ggrid, 256, GEMM_SMEM>>>(x, 0, 2);
    gather_combine_pool<<<nodew_blocks, 256>>>(brel3, batch);

    // head
    mlp_kernel<<<N_GRAPHS, CH>>>(W1, b1, W2, b2, Wo, bo, out);
}

// round 17
// speedup vs baseline: 1.0657x; 1.0657x over previous
#include <cuda_runtime.h>
#include <cuda_bf16.h>
#include <cstdint>

#define N_NODES  50000
#define N_EDGES  800000
#define CH       128
#define N_GRAPHS 512
#define OUT_CH   8
#define NSCAN_BLK 196                     // ceil(50000/256)

// ============================ scratch ==============================================
__device__ __align__(16) float g_h[N_NODES * CH];
__device__ __align__(16) float g_yrel[N_NODES * CH];
__device__ __align__(16) float g_yroot[N_NODES * CH];
__device__ __align__(16) float g_pooled[N_GRAPHS * CH];
__device__ __align__(16) float g_cnt[N_GRAPHS];
__device__ int g_degi[N_NODES];
__device__ int g_rowptr[N_NODES + 1];
__device__ int g_cursor[N_NODES];
__device__ int g_csr[N_EDGES];
__device__ int g_blksum[NSCAN_BLK];
__device__ int g_blkoff[NSCAN_BLK];
// W images: [6 mats][hi|mid][128n][128k] bf16, transposed (n-major) for ldmatrix B frags
__device__ __align__(16) __nv_bfloat16 g_wimg[6 * 2 * CH * CH];

__device__ __forceinline__ uint32_t smem_u32(const void* p) {
    uint32_t a;
    asm("{ .reg .u64 t; cvta.to.shared.u64 t, %1; cvt.u32.u64 %0, t; }" : "=r"(a) : "l"(p));
    return a;
}

// ============================ zero init ============================================
__global__ void zero_kernel() {
    int idx = blockIdx.x * blockDim.x + threadIdx.x;
    if (idx < N_NODES) g_degi[idx] = 0;
    if (idx < N_GRAPHS * CH) g_pooled[idx] = 0.f;
    if (idx < N_GRAPHS) g_cnt[idx] = 0.f;
}

// ============================ degree ===============================================
__global__ void deg_kernel(const int* __restrict__ ei) {
    int e = blockIdx.x * blockDim.x + threadIdx.x;
    if (e < N_EDGES) atomicAdd(&g_degi[ei[N_EDGES + e]], 1);
}

// ============================ CSR build: 3-kernel scan + fill ======================
__global__ void scan1_kernel() {
    __shared__ int s[256];
    int idx = blockIdx.x * 256 + threadIdx.x;
    int v = (idx < N_NODES) ? g_degi[idx] : 0;
    s[threadIdx.x] = v;
    __syncthreads();
    for (int o = 128; o > 0; o >>= 1) {
        if (threadIdx.x < o) s[threadIdx.x] += s[threadIdx.x + o];
        __syncthreads();
    }
    if (threadIdx.x == 0) g_blksum[blockIdx.x] = s[0];
}
__global__ void scan2_kernel() {
    __shared__ int s[256];
    int t = threadIdx.x;
    int v = (t < NSCAN_BLK) ? g_blksum[t] : 0;
    s[t] = v;
    __syncthreads();
    for (int o = 1; o < 256; o <<= 1) {
        int add = (t >= o) ? s[t - o] : 0;
        __syncthreads();
        s[t] += add;
        __syncthreads();
    }
    if (t < NSCAN_BLK) g_blkoff[t] = s[t] - v;
    if (t == 0) g_rowptr[N_NODES] = N_EDGES;
}
__global__ void scan3_kernel() {
    __shared__ int s[256];
    int idx = blockIdx.x * 256 + threadIdx.x;
    int t = threadIdx.x;
    int v = (idx < N_NODES) ? g_degi[idx] : 0;
    s[t] = v;
    __syncthreads();
    for (int o = 1; o < 256; o <<= 1) {
        int add = (t >= o) ? s[t - o] : 0;
        __syncthreads();
        s[t] += add;
        __syncthreads();
    }
    if (idx < N_NODES) {
        int excl = g_blkoff[blockIdx.x] + s[t] - v;
        g_rowptr[idx] = excl;
        g_cursor[idx] = excl;
    }
}
__global__ void fill_kernel(const int* __restrict__ ei) {
    int e = blockIdx.x * blockDim.x + threadIdx.x;
    if (e >= N_EDGES) return;
    int d = ei[N_EDGES + e];
    int pos = atomicAdd(&g_cursor[d], 1);
    g_csr[pos] = ei[e];
}

// ============================ W -> bf16x2 transposed images ========================
__global__ void prep_w(const float* __restrict__ W0, const float* __restrict__ W1,
                       const float* __restrict__ W2, const float* __restrict__ W3,
                       const float* __restrict__ W4, const float* __restrict__ W5) {
    const float* Ws[6] = {W0, W1, W2, W3, W4, W5};
    const float* W = Ws[blockIdx.x];
    __nv_bfloat16* hi = g_wimg + (size_t)blockIdx.x * (2 * CH * CH);
    __nv_bfloat16* md = hi + CH * CH;
    for (int i = threadIdx.x; i < CH * CH; i += blockDim.x) {
        int k = i >> 7, n = i & 127;          // W[k][n]
        float f = W[i];
        __nv_bfloat16 h = __float2bfloat16(f);
        __nv_bfloat16 m = __float2bfloat16(f - __bfloat162float(h));
        hi[n * CH + k] = h;                   // transposed: [n][k]
        md[n * CH + k] = m;
    }
}

// ============================ HMMA dual GEMM (round-13 config) =====================
// grid (391, 2): y = side. CTA tile 128(M) x 128(N), K=128, 2 CTA/SM.
// bf16x2 split (hh + hm + mh). W hi/mid in smem (row stride 272B); A staged per-ks
// through smem as pre-split bf16 hi/mid (128x16, 32B rows, double-buffered).
#define WTILE_B   34816                        // 128 * 272
#define A_STAGE_B 4096                         // 128 rows * 32 B
#define A_BUF_B   (2 * A_STAGE_B)              // hi + mid
#define GEMM_SMEM (2 * WTILE_B + 2 * A_BUF_B)  // 68K + 16K = 84K

__device__ __forceinline__ float4 ldA(const float* A, int mbase, int row, int ks,
                                      int c4, bool tail) {
    int m = mbase + row;
    if (tail && m >= N_NODES) return make_float4(0.f, 0.f, 0.f, 0.f);
    return *(const float4*)(A + (size_t)m * CH + ks * 16 + c4 * 4);
}
__device__ __forceinline__ void stA(char* hi, char* mid, int row, int c4, float4 f) {
    __nv_bfloat162 h01 = __float22bfloat162_rn(make_float2(f.x, f.y));
    __nv_bfloat162 h23 = __float22bfloat162_rn(make_float2(f.z, f.w));
    float2 r01 = make_float2(f.x - __bfloat162float(h01.x), f.y - __bfloat162float(h01.y));
    float2 r23 = make_float2(f.z - __bfloat162float(h23.x), f.w - __bfloat162float(h23.y));
    __nv_bfloat162 m01 = __float22bfloat162_rn(r01);
    __nv_bfloat162 m23 = __float22bfloat162_rn(r23);
    uint2 hv, mv;
    hv.x = *(uint32_t*)&h01; hv.y = *(uint32_t*)&h23;
    mv.x = *(uint32_t*)&m01; mv.y = *(uint32_t*)&m23;
    *(uint2*)(hi  + row * 32 + c4 * 8) = hv;
    *(uint2*)(mid + row * 32 + c4 * 8) = mv;
}

__global__ __launch_bounds__(256, 2)
void gemm_tc(const float* __restrict__ X, int use_x, int layer) {
    extern __shared__ char sm[];
    int tid = threadIdx.x, lane = tid & 31, wid = tid >> 5;
    int mbase = blockIdx.x * 128;
    int side  = blockIdx.y;
    const float* A = use_x ? X : g_h;
    bool tail = (mbase + 128 > N_NODES);

    char* abuf[2][2] = {
        { sm + 2 * WTILE_B,             sm + 2 * WTILE_B + A_STAGE_B },
        { sm + 2 * WTILE_B + A_BUF_B,   sm + 2 * WTILE_B + A_BUF_B + A_STAGE_B } };

    // ---- copy W hi/mid tiles into padded smem -------------------------------------
    {
        const uint4* wh = (const uint4*)(g_wimg + (size_t)(layer * 2 + side) * (2 * CH * CH));
        const uint4* wm = wh + 2048;
        for (int i = tid; i < 2048; i += 256) {
            int r = i >> 4, c = i & 15;
            *(uint4*)(sm + r * 272 + c * 16)           = wh[i];
            *(uint4*)(sm + WTILE_B + r * 272 + c * 16) = wm[i];
        }
    }

    // ---- A stage 0: load, split, store -------------------------------------------
    int prow = tid >> 1;
    int pc0  = (tid & 1) * 2, pc1 = pc0 + 1;
    {
        float4 p0 = ldA(A, mbase, prow, 0, pc0, tail);
        float4 p1 = ldA(A, mbase, prow, 0, pc1, tail);
        stA(abuf[0][0], abuf[0][1], prow, pc0, p0);
        stA(abuf[0][0], abuf[0][1], prow, pc1, p1);
    }
    __syncthreads();

    int mrow = (wid & 3) * 32;
    int ncol = (wid >> 2) * 64;
    uint32_t sb    = smem_u32(sm);
    uint32_t b_off = (uint32_t)(ncol + (lane & 7)) * 272u + (uint32_t)((lane >> 3) & 1) * 16u;
    uint32_t a_lane = (uint32_t)(lane & 15) * 32u + (uint32_t)(lane >> 4) * 16u;
    uint32_t a_base0 = sb + 2u * WTILE_B + (uint32_t)mrow * 32u + a_lane;

    float acc[2][8][4];
    #pragma unroll
    for (int mt = 0; mt < 2; mt++)
        #pragma unroll
        for (int nt = 0; nt < 8; nt++)
            #pragma unroll
            for (int q = 0; q < 4; q++) acc[mt][nt][q] = 0.f;

    #pragma unroll
    for (int ks = 0; ks < 8; ks++) {
        float4 p0, p1;
        if (ks < 7) {
            p0 = ldA(A, mbase, prow, ks + 1, pc0, tail);
            p1 = ldA(A, mbase, prow, ks + 1, pc1, tail);
        }
        uint32_t ahi[2][4], amid[2][4];
        uint32_t ab = a_base0 + (uint32_t)(ks & 1) * A_BUF_B;
        #pragma unroll
        for (int mt = 0; mt < 2; mt++) {
            uint32_t ad = ab + (uint32_t)mt * (16u * 32u);
            asm volatile("ldmatrix.sync.aligned.m8n8.x4.shared.b16 {%0,%1,%2,%3}, [%4];"
                : "=r"(ahi[mt][0]), "=r"(ahi[mt][1]), "=r"(ahi[mt][2]), "=r"(ahi[mt][3])
                : "r"(ad));
            asm volatile("ldmatrix.sync.aligned.m8n8.x4.shared.b16 {%0,%1,%2,%3}, [%4];"
                : "=r"(amid[mt][0]), "=r"(amid[mt][1]), "=r"(amid[mt][2]), "=r"(amid[mt][3])
                : "r"(ad + A_STAGE_B));
        }
        #pragma unroll
        for (int nt = 0; nt < 8; nt++) {
            uint32_t bd = sb + b_off + (uint32_t)nt * (8u * 272u) + (uint32_t)ks * 32u;
            uint32_t bh0, bh1, bm0, bm1;
            asm volatile("ldmatrix.sync.aligned.m8n8.x2.shared.b16 {%0,%1}, [%2];"
                : "=r"(bh0), "=r"(bh1) : "r"(bd));
            asm volatile("ldmatrix.sync.aligned.m8n8.x2.shared.b16 {%0,%1}, [%2];"
                : "=r"(bm0), "=r"(bm1) : "r"(bd + WTILE_B));
            #pragma unroll
            for (int mt = 0; mt < 2; mt++) {
                asm volatile(
                    "mma.sync.aligned.m16n8k16.row.col.f32.bf16.bf16.f32 "
                    "{%0,%1,%2,%3}, {%4,%5,%6,%7}, {%8,%9}, {%0,%1,%2,%3};"
                    : "+f"(acc[mt][nt][0]), "+f"(acc[mt][nt][1]),
                      "+f"(acc[mt][nt][2]), "+f"(acc[mt][nt][3])
                    : "r"(ahi[mt][0]), "r"(ahi[mt][1]), "r"(ahi[mt][2]), "r"(ahi[mt][3]),
                      "r"(bh0), "r"(bh1));
                asm volatile(
                    "mma.sync.aligned.m16n8k16.row.col.f32.bf16.bf16.f32 "
                    "{%0,%1,%2,%3}, {%4,%5,%6,%7}, {%8,%9}, {%0,%1,%2,%3};"
                    : "+f"(acc[mt][nt][0]), "+f"(acc[mt][nt][1]),
                      "+f"(acc[mt][nt][2]), "+f"(acc[mt][nt][3])
                    : "r"(ahi[mt][0]), "r"(ahi[mt][1]), "r"(ahi[mt][2]), "r"(ahi[mt][3]),
                      "r"(bm0), "r"(bm1));
                asm volatile(
                    "mma.sync.aligned.m16n8k16.row.col.f32.bf16.bf16.f32 "
                    "{%0,%1,%2,%3}, {%4,%5,%6,%7}, {%8,%9}, {%0,%1,%2,%3};"
                    : "+f"(acc[mt][nt][0]), "+f"(acc[mt][nt][1]),
                      "+f"(acc[mt][nt][2]), "+f"(acc[mt][nt][3])
                    : "r"(amid[mt][0]), "r"(amid[mt][1]), "r"(amid[mt][2]), "r"(amid[mt][3]),
                      "r"(bh0), "r"(bh1));
            }
        }
        if (ks < 7) {
            char* hb = abuf[(ks + 1) & 1][0];
            char* mb = abuf[(ks + 1) & 1][1];
            stA(hb, mb, prow, pc0, p0);
            stA(hb, mb, prow, pc1, p1);
        }
        __syncthreads();
    }

    // ---- epilogue: fp32 stores ---------------------------------------------------
    float* C = side ? g_yroot : g_yrel;
    int gi = lane >> 2, t4 = lane & 3;
    #pragma unroll
    for (int mt = 0; mt < 2; mt++) {
        int r0 = mbase + mrow + mt * 16 + gi;
        #pragma unroll
        for (int nt = 0; nt < 8; nt++) {
            int col = ncol + nt * 8 + t4 * 2;
            if (r0 < N_NODES)
                *(float2*)(C + (size_t)r0 * CH + col) =
                    make_float2(acc[mt][nt][0], acc[mt][nt][1]);
            if (r0 + 8 < N_NODES)
                *(float2*)(C + (size_t)(r0 + 8) * CH + col) =
                    make_float2(acc[mt][nt][2], acc[mt][nt][3]);
        }
    }
}

// ============================ fused gather + combine (layers 1-2) ==================
__global__ __launch_bounds__(256)
void gather_combine(const float* __restrict__ brel, int do_relu) {
    int gid = blockIdx.x * blockDim.x + threadIdx.x;
    int i   = gid >> 5;
    if (i >= N_NODES) return;
    int lane = gid & 31;
    int beg = g_rowptr[i], end = g_rowptr[i + 1];

    float4 a0 = make_float4(0.f, 0.f, 0.f, 0.f);
    float4 a1 = make_float4(0.f, 0.f, 0.f, 0.f);
    float4 a2 = make_float4(0.f, 0.f, 0.f, 0.f);
    float4 a3 = make_float4(0.f, 0.f, 0.f, 0.f);
    int e = beg;
    for (; e + 3 < end; e += 4) {
        int s0 = g_csr[e], s1 = g_csr[e + 1], s2 = g_csr[e + 2], s3 = g_csr[e + 3];
        float4 v0 = ((const float4*)(g_yrel + (size_t)s0 * CH))[lane];
        float4 v1 = ((const float4*)(g_yrel + (size_t)s1 * CH))[lane];
        float4 v2 = ((const float4*)(g_yrel + (size_t)s2 * CH))[lane];
        float4 v3 = ((const float4*)(g_yrel + (size_t)s3 * CH))[lane];
        a0.x += v0.x; a0.y += v0.y; a0.z += v0.z; a0.w += v0.w;
        a1.x += v1.x; a1.y += v1.y; a1.z += v1.z; a1.w += v1.w;
        a2.x += v2.x; a2.y += v2.y; a2.z += v2.z; a2.w += v2.w;
        a3.x += v3.x; a3.y += v3.y; a3.z += v3.z; a3.w += v3.w;
    }
    for (; e < end; e++) {
        int s0 = g_csr[e];
        float4 v0 = ((const float4*)(g_yrel + (size_t)s0 * CH))[lane];
        a0.x += v0.x; a0.y += v0.y; a0.z += v0.z; a0.w += v0.w;
    }
    float inv = 1.0f / (float)max(end - beg, 1);
    float4 r = ((const float4*)(g_yroot + (size_t)i * CH))[lane];
    float4 b = ((const float4*)brel)[lane];
    float4 o;
    o.x = (a0.x + a1.x + a2.x + a3.x) * inv + r.x + b.x;
    o.y = (a0.y + a1.y + a2.y + a3.y) * inv + r.y + b.y;
    o.z = (a0.z + a1.z + a2.z + a3.z) * inv + r.z + b.z;
    o.w = (a0.w + a1.w + a2.w + a3.w) * inv + r.w + b.w;
    if (do_relu) {
        o.x = fmaxf(o.x, 0.f); o.y = fmaxf(o.y, 0.f);
        o.z = fmaxf(o.z, 0.f); o.w = fmaxf(o.w, 0.f);
    }
    ((float4*)(g_h + (size_t)i * CH))[lane] = o;
}

// ============================ layer 3: gather + combine + pool =====================
__global__ __launch_bounds__(256)
void gather_combine_pool(const float* __restrict__ brel, const int* __restrict__ batch) {
    int gid = blockIdx.x * blockDim.x + threadIdx.x;
    int i   = gid >> 5;
    if (i >= N_NODES) return;
    int lane = gid & 31;
    int beg = g_rowptr[i], end = g_rowptr[i + 1];

    float4 a0 = make_float4(0.f, 0.f, 0.f, 0.f);
    float4 a1 = make_float4(0.f, 0.f, 0.f, 0.f);
    float4 a2 = make_float4(0.f, 0.f, 0.f, 0.f);
    float4 a3 = make_float4(0.f, 0.f, 0.f, 0.f);
    int e = beg;
    for (; e + 3 < end; e += 4) {
        int s0 = g_csr[e], s1 = g_csr[e + 1], s2 = g_csr[e + 2], s3 = g_csr[e + 3];
        float4 v0 = ((const float4*)(g_yrel + (size_t)s0 * CH))[lane];
        float4 v1 = ((const float4*)(g_yrel + (size_t)s1 * CH))[lane];
        float4 v2 = ((const float4*)(g_yrel + (size_t)s2 * CH))[lane];
        float4 v3 = ((const float4*)(g_yrel + (size_t)s3 * CH))[lane];
        a0.x += v0.x; a0.y += v0.y; a0.z += v0.z; a0.w += v0.w;
        a1.x += v1.x; a1.y += v1.y; a1.z += v1.z; a1.w += v1.w;
        a2.x += v2.x; a2.y += v2.y; a2.z += v2.z; a2.w += v2.w;
        a3.x += v3.x; a3.y += v3.y; a3.z += v3.z; a3.w += v3.w;
    }
    for (; e < end; e++) {
        int s0 = g_csr[e];
        float4 v0 = ((const float4*)(g_yrel + (size_t)s0 * CH))[lane];
        a0.x += v0.x; a0.y += v0.y; a0.z += v0.z; a0.w += v0.w;
    }
    float inv = 1.0f / (float)max(end - beg, 1);
    float4 r = ((const float4*)(g_yroot + (size_t)i * CH))[lane];
    float4 b = ((const float4*)brel)[lane];
    float4 o;
    o.x = (a0.x + a1.x + a2.x + a3.x) * inv + r.x + b.x;
    o.y = (a0.y + a1.y + a2.y + a3.y) * inv + r.y + b.y;
    o.z = (a0.z + a1.z + a2.z + a3.z) * inv + r.z + b.z;
    o.w = (a0.w + a1.w + a2.w + a3.w) * inv + r.w + b.w;
    int bg = batch[i];
    float* p = g_pooled + (size_t)bg * CH + lane * 4;
    asm volatile("red.global.add.v4.f32 [%0], {%1, %2, %3, %4};"
                 :: "l"(p), "f"(o.x), "f"(o.y), "f"(o.z), "f"(o.w) : "memory");
    if (lane == 0) atomicAdd(&g_cnt[bg], 1.0f);
}

// ============================ MLP head =============================================
__global__ void mlp_kernel(const float* __restrict__ W1, const float* __restrict__ b1,
                           const float* __restrict__ W2, const float* __restrict__ b2,
                           const float* __restrict__ Wo, const float* __restrict__ bo,
                           float* __restrict__ out) {
    __shared__ float s0[CH], s1[CH];
    int b = blockIdx.x, t = threadIdx.x;
    float c = fmaxf(g_cnt[b], 1.0f);
    s0[t] = g_pooled[b * CH + t] / c;
    __syncthreads();
    float acc = b1[t];
    #pragma unroll 8
    for (int k = 0; k < CH; k++) acc += s0[k] * W1[k * CH + t];
    s1[t] = fmaxf(acc, 0.f);
    __syncthreads();
    acc = b2[t];
    #pragma unroll 8
    for (int k = 0; k < CH; k++) acc += s1[k] * W2[k * CH + t];
    __syncthreads();
    s0[t] = fmaxf(acc, 0.f);
    __syncthreads();
    if (t < OUT_CH) {
        float a = bo[t];
        #pragma unroll 8
        for (int k = 0; k < CH; k++) a += s0[k] * Wo[k * OUT_CH + t];
        out[b * OUT_CH + t] = a;
    }
}

// ============================ launch ===============================================
extern "C" void kernel_launch(void* const* d_in, const int* in_sizes, int n_in,
                              void* d_out, int out_size) {
    const float* x     = (const float*)d_in[0];
    const int*   ei    = (const int*)d_in[1];
    const int*   batch = (const int*)d_in[2];
    const float* Wrel1 = (const float*)d_in[3];
    const float* brel1 = (const float*)d_in[4];
    const float* Wroot1= (const float*)d_in[5];
    const float* Wrel2 = (const float*)d_in[6];
    const float* brel2 = (const float*)d_in[7];
    const float* Wroot2= (const float*)d_in[8];
    const float* Wrel3 = (const float*)d_in[9];
    const float* brel3 = (const float*)d_in[10];
    const float* Wroot3= (const float*)d_in[11];
    const float* W1 = (const float*)d_in[12];
    const float* b1 = (const float*)d_in[13];
    const float* W2 = (const float*)d_in[14];
    const float* b2 = (const float*)d_in[15];
    const float* Wo = (const float*)d_in[16];
    const float* bo = (const float*)d_in[17];
    float* out = (float*)d_out;

    static int inited = 0;
    static cudaStream_t s1;
    static cudaEvent_t evFork, evJoin;
    if (!inited) {
        cudaFuncSetAttribute(gemm_tc, cudaFuncAttributeMaxDynamicSharedMemorySize, GEMM_SMEM);
        cudaStreamCreateWithFlags(&s1, cudaStreamNonBlocking);
        cudaEventCreateWithFlags(&evFork, cudaEventDisableTiming);
        cudaEventCreateWithFlags(&evJoin, cudaEventDisableTiming);
        inited = 1;
    }

    dim3 ggrid((N_NODES + 127) / 128, 2);                       // 391 x 2
    const int nodew_blocks = (N_NODES * 32 + 255) / 256;        // 6250

    // ---- fork: side stream runs prep_w + gemm layer 1 (needs only x, W) ----------
    cudaEventRecord(evFork, 0);
    cudaStreamWaitEvent(s1, evFork, 0);
    prep_w<<<6, 256, 0, s1>>>(Wrel1, Wroot1, Wrel2, Wroot2, Wrel3, Wroot3);
    gemm_tc<<<ggrid, 256, GEMM_SMEM, s1>>>(x, 1, 0);

    // ---- null stream: CSR build (independent of gemm1) ----------------------------
    zero_kernel<<<(N_GRAPHS * CH + 255) / 256, 256>>>();
    deg_kernel<<<(N_EDGES + 255) / 256, 256>>>(ei);
    scan1_kernel<<<NSCAN_BLK, 256>>>();
    scan2_kernel<<<1, 256>>>();
    scan3_kernel<<<NSCAN_BLK, 256>>>();
    fill_kernel<<<(N_EDGES + 255) / 256, 256>>>(ei);

    // ---- join ---------------------------------------------------------------------
    cudaEventRecord(evJoin, s1);
    cudaStreamWaitEvent(0, evJoin, 0);

    // layer 1 combine
    gather_combine<<<nodew_blocks, 256>>>(brel1, 1);
    // layer 2
    gemm_tc<<<ggrid, 256, GEMM_SMEM>>>(x, 0, 1);
    gather_combine<<<nodew_blocks, 256>>>(brel2, 1);
    // layer 3: gather + combine + pool fused
    gemm_tc<<<ggrid, 256, GEMM_SMEM>>>(x, 0, 2);
    gather_combine_pool<<<nodew_blocks, 256>>>(brel3, batch);

    // head
    mlp_kernel<<<N_GRAPHS, CH>>>(W1, b1, W2, b2, Wo, bo, out);
}